// round 12
// baseline (speedup 1.0000x reference)
#include <cuda_runtime.h>
#include <cuda_bf16.h>
#include <cstdint>
#include <math.h>

// Problem constants
#define BB 64
#define SS 512
#define II 512
#define HH 512
#define LL 2
#define MROWS (BB * LL)          // 128 recurrence rows
#define MX (BB * SS)             // 32768 rows of xa GEMM

// ---------------- scratch (static device memory; no allocs allowed) ----------
__device__ float g_xa[(size_t)MX * HH];       // 64 MB: xa = x @ W_ih^T + b_ih
__device__ float g_h[2][MROWS * HH];          // double-buffered recurrent state

// per-row-group barrier state (16 groups of 8 CTAs), padded slots
#define RB_GROUPS 16
__device__ unsigned g_cnt[RB_GROUPS * 32];    // arrival counts (return to 0)
__device__ unsigned g_sense[RB_GROUPS * 32];  // 512 toggles -> back to 0

__device__ __forceinline__ unsigned cvt_tf32(float f) {
    unsigned u;
    asm("cvt.rna.tf32.f32 %0, %1;" : "=r"(u) : "f"(f));
    return u;
}

// =============================================================================
// Kernel A: xa[m][n] = sum_k x[m][k] * W_ih[n][k] + b_ih[n]   via tf32 mma.sync
// (unchanged from round 9 — proven)
// =============================================================================
__global__ void __launch_bounds__(256) gemm_xa_mma_kernel(
    const float* __restrict__ X,      // [MX][II]
    const float* __restrict__ Wih,    // [HH][II]
    const float* __restrict__ bias)   // [HH]
{
    const int m0   = blockIdx.y * 128;
    const int n0   = blockIdx.x * 128;
    const int w    = threadIdx.x >> 5;
    const int lane = threadIdx.x & 31;
    const int g    = lane >> 2;        // groupID 0..7
    const int t    = lane & 3;         // thread-in-group 0..3
    const int wr   = w >> 2;           // 0..1  -> 64 m-rows
    const int wc   = w & 3;            // 0..3  -> 32 n-cols
    const int mbase = m0 + wr * 64;
    const int nbase = n0 + wc * 32;

    float acc[4][4][4];
#pragma unroll
    for (int mf = 0; mf < 4; mf++)
#pragma unroll
        for (int nf = 0; nf < 4; nf++)
#pragma unroll
            for (int r = 0; r < 4; r++) acc[mf][nf][r] = 0.f;

    const float* Xa = X + (size_t)(mbase + g) * II;
    const float* Xb = X + (size_t)(mbase + g + 8) * II;
    const float* Wb = Wih + (size_t)(nbase + g) * II;

#pragma unroll 2
    for (int kt = 0; kt < 64; kt++) {
        const int k0 = kt * 8;

        unsigned a[4][4];
#pragma unroll
        for (int mf = 0; mf < 4; mf++) {
            const int ro = mf * 16 * II;
            a[mf][0] = cvt_tf32(__ldg(Xa + ro + k0 + t));
            a[mf][1] = cvt_tf32(__ldg(Xb + ro + k0 + t));
            a[mf][2] = cvt_tf32(__ldg(Xa + ro + k0 + t + 4));
            a[mf][3] = cvt_tf32(__ldg(Xb + ro + k0 + t + 4));
        }
        unsigned b[4][2];
#pragma unroll
        for (int nf = 0; nf < 4; nf++) {
            const int no = nf * 8 * II;
            b[nf][0] = cvt_tf32(__ldg(Wb + no + k0 + t));
            b[nf][1] = cvt_tf32(__ldg(Wb + no + k0 + t + 4));
        }
#pragma unroll
        for (int mf = 0; mf < 4; mf++)
#pragma unroll
            for (int nf = 0; nf < 4; nf++) {
                asm volatile(
                    "mma.sync.aligned.m16n8k8.row.col.f32.tf32.tf32.f32 "
                    "{%0,%1,%2,%3}, {%4,%5,%6,%7}, {%8,%9}, {%0,%1,%2,%3};"
                    : "+f"(acc[mf][nf][0]), "+f"(acc[mf][nf][1]),
                      "+f"(acc[mf][nf][2]), "+f"(acc[mf][nf][3])
                    : "r"(a[mf][0]), "r"(a[mf][1]), "r"(a[mf][2]), "r"(a[mf][3]),
                      "r"(b[nf][0]), "r"(b[nf][1]));
            }
    }

#pragma unroll
    for (int nf = 0; nf < 4; nf++) {
        const int col = nbase + nf * 8 + 2 * t;
        const float2 bv = *(const float2*)&bias[col];
#pragma unroll
        for (int mf = 0; mf < 4; mf++) {
            const int row0 = mbase + mf * 16 + g;
            float2 d01, d23;
            d01.x = acc[mf][nf][0] + bv.x;
            d01.y = acc[mf][nf][1] + bv.y;
            d23.x = acc[mf][nf][2] + bv.x;
            d23.y = acc[mf][nf][3] + bv.y;
            *(float2*)&g_xa[(size_t)row0 * HH + col]       = d01;
            *(float2*)&g_xa[(size_t)(row0 + 8) * HH + col] = d23;
        }
    }
}

// =============================================================================
// Kernel B: persistent recurrence, v7 (tensor-core, register-resident W).
// 128 CTAs = 16 row-groups (rb) x 8 col-blocks (gb).
// CTA (rb,gb): batch rows rb*8..+7 (n), W cols gb*64..+63 (m), K=512.
// 8 warps = 4 m-tiles (mw) x 2 k-halves (kw, 256 k each = 32 k8 slices).
// W tf32 A-fragments live in REGISTERS for all 512 steps (128 regs/thread).
// Per step: stage h (8x512) to smem as tf32, 32 mma per warp (b-frags via
// conflict-free LDS.32), 2-way k-half reduce through smem, tanh, publish.
// Barrier identical to round-3 (per-row-group, 8 CTAs).
// D[m][n]: m = W col, n = batch row.  mma m16n8k8 row.col:
//   A(i,k) = W_hh[g0+mtile+i][k],  B(k,n) = h[n][k]
//   a0(g,t) a1(g+8,t) a2(g,t+4) a3(g+8,t+4);  b0 = h[g][t], b1 = h[g][t+4]
//   d0(g,2t) d1(g,2t+1) d2(g+8,2t) d3(g+8,2t+1)
// =============================================================================
#define GB_CTAS 128
#define GRP 8

__global__ void __launch_bounds__(256, 1) rnn_persistent_kernel(
    const float* __restrict__ W_hh,   // [HH][HH]
    const float* __restrict__ b_hh,   // [HH]
    float* __restrict__ out)          // y then h_last
{
    __shared__ unsigned hsu[8 * 516];     // staged h rows, tf32, padded
    __shared__ float red[2 * 64 * 8];     // [kw][m][n]

    const int tid  = threadIdx.x;
    const int w    = tid >> 5;
    const int lane = tid & 31;
    const int g    = lane >> 2;        // 0..7
    const int t    = lane & 3;         // 0..3
    const int mw   = w & 3;            // m-tile 0..3
    const int kw   = w >> 2;           // k-half 0..1
    const int kb   = kw * 256;

    const int gb  = blockIdx.x & 7;
    const int rb  = blockIdx.x >> 3;
    const int g0  = gb * 64;
    const int row_base = rb * 8;

    // ---- one-time: load this warp's W A-fragments into registers ----
    unsigned wa[32][4];
    {
        const float* w0p = W_hh + (size_t)(g0 + mw * 16 + g) * HH + kb;
        const float* w1p = w0p + 8 * HH;
#pragma unroll
        for (int ks = 0; ks < 32; ks++) {
            wa[ks][0] = cvt_tf32(__ldg(w0p + ks * 8 + t));
            wa[ks][1] = cvt_tf32(__ldg(w1p + ks * 8 + t));
            wa[ks][2] = cvt_tf32(__ldg(w0p + ks * 8 + t + 4));
            wa[ks][3] = cvt_tf32(__ldg(w1p + ks * 8 + t + 4));
        }
    }

    // ---- epilogue mapping (round-3): outputs (n=orow, m=oc, oc+1) ----
    const int orow  = tid >> 5;        // batch row 0..7
    const int oc    = 2 * (tid & 31);  // W col pair 0..62
    const int grow  = row_base + orow;
    const int b_idx = grow >> 1;
    const int l_idx = grow & 1;
    const int gcol  = g0 + oc;

    const float2 bg  = *(const float2*)&b_hh[gcol];
    float2 xav = *(const float2*)&g_xa[((size_t)b_idx * SS + 0) * HH + gcol];

    unsigned* cnt = &g_cnt[rb * 32];
    unsigned* sns = &g_sense[rb * 32];
    unsigned  sense = 0;

    const size_t Y_ELEMS = (size_t)BB * SS * LL * HH;
    __syncthreads();

    for (int s = 0; s < SS; s++) {
        float v0, v1;
        if (s == 0) {
            v0 = tanhf(xav.x + bg.x);
            v1 = tanhf(xav.y + bg.y);
        } else {
            // wait for group (8 CTAs sharing rb) to finish step s-1
            if (tid == 0) {
                unsigned v;
                do {
                    asm volatile("ld.acquire.gpu.u32 %0, [%1];"
                                 : "=r"(v) : "l"(sns));
                } while (v != sense);
            }
            __syncthreads();

            // stage h rows (8 x 512) from L2, converting to tf32
            {
                const float4* src =
                    (const float4*)(&g_h[s & 1][(size_t)row_base * HH]);
#pragma unroll
                for (int j = 0; j < 4; j++) {
                    const int idx = tid + j * 256;      // 0..1023 float4s
                    const int r   = idx >> 7;
                    const int kk  = (idx & 127) * 4;
                    const float4 hv = __ldcg(src + idx);
                    uint4 u;
                    u.x = cvt_tf32(hv.x); u.y = cvt_tf32(hv.y);
                    u.z = cvt_tf32(hv.z); u.w = cvt_tf32(hv.w);
                    *(uint4*)&hsu[r * 516 + kk] = u;
                }
            }
            __syncthreads();

            // tensor-core accumulate over this warp's 32 k-slices
            float a0 = 0.f, a1 = 0.f, a2 = 0.f, a3 = 0.f;
            const unsigned* hb = hsu + g * 516 + kb + t;
#pragma unroll
            for (int ks = 0; ks < 32; ks++) {
                const unsigned b0 = hb[ks * 8];
                const unsigned b1 = hb[ks * 8 + 4];
                asm volatile(
                    "mma.sync.aligned.m16n8k8.row.col.f32.tf32.tf32.f32 "
                    "{%0,%1,%2,%3}, {%4,%5,%6,%7}, {%8,%9}, {%0,%1,%2,%3};"
                    : "+f"(a0), "+f"(a1), "+f"(a2), "+f"(a3)
                    : "r"(wa[ks][0]), "r"(wa[ks][1]),
                      "r"(wa[ks][2]), "r"(wa[ks][3]),
                      "r"(b0), "r"(b1));
            }

            // scatter partials: red[kw][m][n]
            {
                float* rp = red + kw * 512;
                *(float2*)&rp[(mw * 16 + g) * 8 + 2 * t]     = make_float2(a0, a1);
                *(float2*)&rp[(mw * 16 + g + 8) * 8 + 2 * t] = make_float2(a2, a3);
            }
            __syncthreads();

            // k-half reduce for outputs (m=oc,oc+1; n=orow)
            const float s0 = red[oc * 8 + orow]       + red[512 + oc * 8 + orow];
            const float s1 = red[(oc + 1) * 8 + orow] + red[512 + (oc + 1) * 8 + orow];
            v0 = tanhf(s0 + xav.x + bg.x);
            v1 = tanhf(s1 + xav.y + bg.y);
        }

        // publish h for next step (straight to L2)
        {
            float2* hdst = (float2*)&g_h[(s + 1) & 1][(size_t)grow * HH + gcol];
            asm volatile("st.global.cg.v2.f32 [%0], {%1, %2};"
                         :: "l"(hdst), "f"(v0), "f"(v1));
        }
        __syncthreads();

        // group barrier arrival (release publishes this step's h writes)
        if (tid == 0) {
            unsigned old;
            asm volatile("atom.add.release.gpu.u32 %0, [%1], %2;"
                         : "=r"(old) : "l"(cnt), "r"(1u));
            if (old == GRP - 1u) {
                asm volatile("st.relaxed.gpu.u32 [%0], %1;"
                             :: "l"(cnt), "r"(0u));
                asm volatile("st.release.gpu.u32 [%0], %1;"
                             :: "l"(sns), "r"(sense ^ 1u));
            }
        }
        sense ^= 1u;

        // epilogue overlaps peers' spin: y writes + next xa prefetch
        {
            float2 yv; yv.x = v0; yv.y = v1;
            *(float2*)&out[(((size_t)b_idx * SS + s) * LL + l_idx) * HH + gcol] = yv;
            if (s == SS - 1) {
                *(float2*)&out[Y_ELEMS + (size_t)grow * HH + gcol] = yv;
            } else {
                xav = *(const float2*)&g_xa[((size_t)b_idx * SS + (s + 1)) * HH + gcol];
            }
        }
    }
}

// =============================================================================
// launch
// =============================================================================
extern "C" void kernel_launch(void* const* d_in, const int* in_sizes, int n_in,
                              void* d_out, int out_size)
{
    const float* x    = (const float*)d_in[0];
    const float* W_ih = (const float*)d_in[1];
    const float* b_ih = (const float*)d_in[2];
    const float* W_hh = (const float*)d_in[3];
    const float* b_hh = (const float*)d_in[4];
    float* out = (float*)d_out;

    // Kernel A: xa = x @ W_ih^T + b_ih  (tf32 mma.sync)
    dim3 gridA(HH / 128, MX / 128);   // (4, 256)
    gemm_xa_mma_kernel<<<gridA, 256>>>(x, W_ih, b_ih);

    // Kernel B: persistent recurrence (tensor-core, register-resident W)
    rnn_persistent_kernel<<<GB_CTAS, 256>>>(W_hh, b_hh, out);
}